// round 13
// baseline (speedup 1.0000x reference)
#include <cuda_runtime.h>
#include <cuda_bf16.h>
#include <cstdint>

// Problem constants
#define Bv 64
#define Cv 256
#define Nv 307
#define Tv 12
#define NT (Nv * Tv)     // 3684
#define NT4 (NT / 4)     // 921

// Scratch (device globals: allocation-free rule)
__device__ float g_k[Bv * Cv * Tv];             // pooled k: [B, C, T]
__device__ float g_attT[(size_t)Bv * Cv * Cv];  // softmax(att) TRANSPOSED: [b][k][m]

// ---------------------------------------------------------------------------
// helpers
// ---------------------------------------------------------------------------
__device__ __forceinline__ uint32_t smem_u32(const void* p) {
    uint32_t a;
    asm("{ .reg .u64 t; cvta.to.shared.u64 t, %1; cvt.u32.u64 %0, t; }" : "=r"(a) : "l"(p));
    return a;
}
// pack two floats as bf16x2 (low half = first arg)
__device__ __forceinline__ uint32_t bpack(float f0, float f1) {
    unsigned short u0 = __bfloat16_as_ushort(__float2bfloat16(f0));
    unsigned short u1 = __bfloat16_as_ushort(__float2bfloat16(f1));
    return (uint32_t)u0 | ((uint32_t)u1 << 16);
}
__device__ __forceinline__ float bres(float f) {   // residual after bf16 truncation
    return f - __bfloat162float(__float2bfloat16(f));
}
__device__ __forceinline__ void ldsm_x4_t(uint32_t& r0, uint32_t& r1, uint32_t& r2,
                                          uint32_t& r3, uint32_t addr) {
    asm volatile("ldmatrix.sync.aligned.m8n8.x4.trans.shared.b16 {%0,%1,%2,%3}, [%4];"
                 : "=r"(r0), "=r"(r1), "=r"(r2), "=r"(r3) : "r"(addr));
}
__device__ __forceinline__ void ldsm_x2_t(uint32_t& r0, uint32_t& r1, uint32_t addr) {
    asm volatile("ldmatrix.sync.aligned.m8n8.x2.trans.shared.b16 {%0,%1}, [%2];"
                 : "=r"(r0), "=r"(r1) : "r"(addr));
}
__device__ __forceinline__ void mma_bf16(float* c, uint32_t a0, uint32_t a1, uint32_t a2,
                                         uint32_t a3, uint32_t b0, uint32_t b1) {
    asm volatile(
        "mma.sync.aligned.m16n8k16.row.col.f32.bf16.bf16.f32 "
        "{%0,%1,%2,%3}, {%4,%5,%6,%7}, {%8,%9}, {%0,%1,%2,%3};"
        : "+f"(c[0]), "+f"(c[1]), "+f"(c[2]), "+f"(c[3])
        : "r"(a0), "r"(a1), "r"(a2), "r"(a3), "r"(b0), "r"(b1));
}

// ---------------------------------------------------------------------------
// Stage 1 (v3): pooling  (measured 42.8us @ 72% DRAM -- at roofline, frozen)
// ---------------------------------------------------------------------------
__global__ __launch_bounds__(384) void pool_kernel(const float* __restrict__ x,
                                                   const float* __restrict__ alpha) {
    __shared__ float a_sm[Nv];
    __shared__ float4 red4[384];
    const int tid = threadIdx.x;
    const int r   = tid / 96;
    const int f0  = tid % 96;
    const int bc  = blockIdx.x * 4 + r;

    for (int i = tid; i < Nv; i += 384) a_sm[i] = alpha[i];
    __syncthreads();

    const float4* xp4 = reinterpret_cast<const float4*>(x) + (size_t)bc * NT4;
    const int i0 = f0 / 3;

    float4 acc = make_float4(0.f, 0.f, 0.f, 0.f);
    {
        float4 vv[5]; float aa[5];
#pragma unroll
        for (int u = 0; u < 5; u++) vv[u] = xp4[f0 + u * 96];
#pragma unroll
        for (int u = 0; u < 5; u++) aa[u] = a_sm[i0 + u * 32];
#pragma unroll
        for (int u = 0; u < 5; u++) {
            acc.x += aa[u] * vv[u].x;  acc.y += aa[u] * vv[u].y;
            acc.z += aa[u] * vv[u].z;  acc.w += aa[u] * vv[u].w;
        }
    }
    {
        float4 vv[4]; float aa[4];
#pragma unroll
        for (int u = 0; u < 4; u++) vv[u] = xp4[f0 + (5 + u) * 96];
#pragma unroll
        for (int u = 0; u < 4; u++) aa[u] = a_sm[i0 + (5 + u) * 32];
#pragma unroll
        for (int u = 0; u < 4; u++) {
            acc.x += aa[u] * vv[u].x;  acc.y += aa[u] * vv[u].y;
            acc.z += aa[u] * vv[u].z;  acc.w += aa[u] * vv[u].w;
        }
    }
    if (f0 + 9 * 96 < NT4) {
        const float a = a_sm[i0 + 9 * 32];
        const float4 v = xp4[f0 + 9 * 96];
        acc.x += a * v.x;  acc.y += a * v.y;
        acc.z += a * v.z;  acc.w += a * v.w;
    }

    red4[tid] = acc;
    __syncthreads();

    if (tid < 48) {
        const int r2 = tid / Tv;
        const int t  = tid % Tv;
        const int g  = t / 4;
        const int e  = t % 4;
        float s = 0.f;
#pragma unroll
        for (int m = 0; m < 32; m++) {
            const float4 v = red4[r2 * 96 + g + 3 * m];
            s += e == 0 ? v.x : (e == 1 ? v.y : (e == 2 ? v.z : v.w));
        }
        g_k[(blockIdx.x * 4 + r2) * Tv + t] = s;
    }
}

// ---------------------------------------------------------------------------
// Stage 2: att = softmax_d(kW k^T), stored TRANSPOSED g_attT[b][d][c]
// ---------------------------------------------------------------------------
__global__ void att_kernel(const float* __restrict__ W) {
    __shared__ float k_sm[Cv * Tv];
    __shared__ float W_sm[Tv * Tv];
    const int b = blockIdx.x;
    const int c = threadIdx.x;

    for (int i = c; i < Cv * Tv; i += Cv) k_sm[i] = g_k[b * Cv * Tv + i];
    if (c < Tv * Tv) W_sm[c] = W[c];
    __syncthreads();

    float kw[Tv];
#pragma unroll
    for (int t = 0; t < Tv; t++) {
        float s = 0.f;
#pragma unroll
        for (int ss = 0; ss < Tv; ss++) s += k_sm[c * Tv + ss] * W_sm[ss * Tv + t];
        kw[t] = s;
    }

    float m = -1e30f;
    for (int d = 0; d < Cv; d++) {
        float s = 0.f;
#pragma unroll
        for (int t = 0; t < Tv; t++) s += kw[t] * k_sm[d * Tv + t];
        m = fmaxf(m, s);
    }

    float* attT = g_attT + (size_t)b * Cv * Cv;
    float Z = 0.f;
    for (int d = 0; d < Cv; d++) {
        float s = 0.f;
#pragma unroll
        for (int t = 0; t < Tv; t++) s += kw[t] * k_sm[d * Tv + t];
        float e = expf(s - m);
        attT[d * Cv + c] = e;
        Z += e;
    }

    const float inv = 1.f / Z;
    for (int d = 0; d < Cv; d++) attT[d * Cv + c] *= inv;
}

// ---------------------------------------------------------------------------
// Stage 3 (mma.sync bf16 hi/lo split, BN=128): out[b] = att[b] @ x[b]
// CTA: 128m x 128n x 32k, 256 thr, 8 warps (2m x 4n), warp tile 64m x 32n.
// Per k16: B frags (4 ns, hi/lo) loaded once, reused over 4 ms subtiles.
// 3-term split: D += Ah*Bh + Ah*Bl + Al*Bh (al*bl dropped, ~2^-18).
// ---------------------------------------------------------------------------
#define BMm 128
#define BNm 128
#define BKm 32
#define KSTEPS (Cv / BKm)   // 8
#define APITCH 272          // 128 bf16 + 8 pad
#define BPITCH 272          // 128 bf16 + 8 pad

__global__ __launch_bounds__(256) void mix_mma_kernel(const float* __restrict__ x,
                                                      float* __restrict__ out) {
    __shared__ __align__(16) unsigned char Ah[BKm * APITCH];
    __shared__ __align__(16) unsigned char Al[BKm * APITCH];
    __shared__ __align__(16) unsigned char Bh[BKm * BPITCH];
    __shared__ __align__(16) unsigned char Bl[BKm * BPITCH];

    const int tid  = threadIdx.x;
    const int wid  = tid >> 5;
    const int lane = tid & 31;
    const int b    = blockIdx.z;
    const int m0g  = blockIdx.y * BMm;
    const int n0g  = blockIdx.x * BNm;
    const int m_w  = (wid & 1) * 64;   // warp m offset (2 m-warps, 64 rows)
    const int n_w  = (wid >> 1) * 32;  // warp n offset (4 n-warps, 32 cols)

    const float* AT = g_attT + (size_t)b * Cv * Cv;  // [k=256][m=256]
    const float* Bx = x + (size_t)b * Cv * NT;       // [k=256][n=3684]
    float*       O  = out + (size_t)b * Cv * NT;

    const uint32_t sAh = smem_u32(Ah), sAl = smem_u32(Al);
    const uint32_t sBh = smem_u32(Bh), sBl = smem_u32(Bl);

    float acc[4][4][4] = {};   // [msub(16)][nsub(8)][frag]

    // staging registers
    float4 aS[4], bS[4];

    // loaders (256 thr): pass p -> k = p*8 + wid, col = lane*4  (both tiles)
    const int kl = wid;            // + p*8
    const int cl = lane * 4;

    // ---- prologue: load tile 0 ----
#pragma unroll
    for (int p = 0; p < 4; p++)
        aS[p] = *reinterpret_cast<const float4*>(AT + (size_t)(p * 8 + kl) * Cv + m0g + cl);
#pragma unroll
    for (int p = 0; p < 4; p++) {
        const int gn = n0g + cl;
        float4 v = make_float4(0.f, 0.f, 0.f, 0.f);
        if (gn < NT)   // NT % 4 == 0: float4-safe predication
            v = *reinterpret_cast<const float4*>(Bx + (size_t)(p * 8 + kl) * NT + gn);
        bS[p] = v;
    }

#pragma unroll 1
    for (int it = 0; it < KSTEPS; it++) {
        if (it) __syncthreads();   // all warps finished MMA on previous tile

        // ---- STS: convert fp32 -> bf16 hi/lo ----
#pragma unroll
        for (int p = 0; p < 4; p++) {
            const float4 v = aS[p];
            const int off = (p * 8 + kl) * APITCH + cl * 2;
            *reinterpret_cast<uint2*>(Ah + off) =
                make_uint2(bpack(v.x, v.y), bpack(v.z, v.w));
            *reinterpret_cast<uint2*>(Al + off) =
                make_uint2(bpack(bres(v.x), bres(v.y)), bpack(bres(v.z), bres(v.w)));
        }
#pragma unroll
        for (int p = 0; p < 4; p++) {
            const float4 v = bS[p];
            const int off = (p * 8 + kl) * BPITCH + cl * 2;
            *reinterpret_cast<uint2*>(Bh + off) =
                make_uint2(bpack(v.x, v.y), bpack(v.z, v.w));
            *reinterpret_cast<uint2*>(Bl + off) =
                make_uint2(bpack(bres(v.x), bres(v.y)), bpack(bres(v.z), bres(v.w)));
        }
        __syncthreads();

        // ---- prefetch next tile (overlaps MMA below) ----
        if (it + 1 < KSTEPS) {
            const int k0 = (it + 1) * BKm;
#pragma unroll
            for (int p = 0; p < 4; p++)
                aS[p] = *reinterpret_cast<const float4*>(
                    AT + (size_t)(k0 + p * 8 + kl) * Cv + m0g + cl);
#pragma unroll
            for (int p = 0; p < 4; p++) {
                const int gn = n0g + cl;
                float4 v = make_float4(0.f, 0.f, 0.f, 0.f);
                if (gn < NT)
                    v = *reinterpret_cast<const float4*>(
                        Bx + (size_t)(k0 + p * 8 + kl) * NT + gn);
                bS[p] = v;
            }
        }

        // ---- MMA over this tile: 2 k16 steps ----
#pragma unroll
        for (int ks = 0; ks < 2; ks++) {
            // B fragments first (held across ms loop):
            // ldmatrix.x2.trans lanes 0-7:(k0-7,n), 8-15:(k8-15,n)
            const int bkk = ks * 16 + (lane & 15);
            uint32_t bh[4][2], bl[4][2];
#pragma unroll
            for (int ns = 0; ns < 4; ns++) {
                const uint32_t o = (uint32_t)(bkk * BPITCH + (n_w + ns * 8) * 2);
                ldsm_x2_t(bh[ns][0], bh[ns][1], sBh + o);
                ldsm_x2_t(bl[ns][0], bl[ns][1], sBl + o);
            }
            // A fragments per ms (transient):
            // ldmatrix.x4.trans lanes 0-7:(k0-7,m), 8-15:(k0-7,m+8),
            //                   16-23:(k8-15,m), 24-31:(k8-15,m+8)
            const int kk = ks * 16 + (lane & 7) + ((lane & 16) >> 1);
#pragma unroll
            for (int ms = 0; ms < 4; ms++) {
                const int mm = m_w + ms * 16 + (lane & 8);
                const uint32_t o = (uint32_t)(kk * APITCH + mm * 2);
                uint32_t ah[4], al[4];
                ldsm_x4_t(ah[0], ah[1], ah[2], ah[3], sAh + o);
                ldsm_x4_t(al[0], al[1], al[2], al[3], sAl + o);
#pragma unroll
                for (int ns = 0; ns < 4; ns++) {
                    mma_bf16(acc[ms][ns], ah[0], ah[1], ah[2], ah[3],
                             bh[ns][0], bh[ns][1]);
                    mma_bf16(acc[ms][ns], ah[0], ah[1], ah[2], ah[3],
                             bl[ns][0], bl[ns][1]);
                    mma_bf16(acc[ms][ns], al[0], al[1], al[2], al[3],
                             bh[ns][0], bh[ns][1]);
                }
            }
        }
    }

    // ---- epilogue ----
    // c0,c1: (row = lane/4, col = (lane%4)*2 + {0,1}); c2,c3: row+8
#pragma unroll
    for (int ms = 0; ms < 4; ms++)
#pragma unroll
        for (int ns = 0; ns < 4; ns++) {
            const int row = m0g + m_w + ms * 16 + (lane >> 2);
            const int col = n0g + n_w + ns * 8 + (lane & 3) * 2;
            if (col < NT) {
                float2 v0 = make_float2(acc[ms][ns][0], acc[ms][ns][1]);
                float2 v1 = make_float2(acc[ms][ns][2], acc[ms][ns][3]);
                *reinterpret_cast<float2*>(O + (size_t)row * NT + col) = v0;
                *reinterpret_cast<float2*>(O + (size_t)(row + 8) * NT + col) = v1;
            }
        }
}

// ---------------------------------------------------------------------------
extern "C" void kernel_launch(void* const* d_in, const int* in_sizes, int n_in,
                              void* d_out, int out_size) {
    const float* x     = (const float*)d_in[0];  // [64,256,307,12]
    const float* W     = (const float*)d_in[1];  // [12,12]
    const float* alpha = (const float*)d_in[2];  // [307]
    float*       out   = (float*)d_out;          // [64,256,307,12]

    pool_kernel<<<Bv * Cv / 4, 384>>>(x, alpha);
    att_kernel<<<Bv, Cv>>>(W);

    dim3 grid((NT + BNm - 1) / BNm, Cv / BMm, Bv);  // (29, 2, 64)
    mix_mma_kernel<<<grid, 256>>>(x, out);
}

// round 15
// speedup vs baseline: 1.1177x; 1.1177x over previous
#include <cuda_runtime.h>
#include <cuda_bf16.h>
#include <cstdint>

// Problem constants
#define Bv 64
#define Cv 256
#define Nv 307
#define Tv 12
#define NT (Nv * Tv)     // 3684
#define NT4 (NT / 4)     // 921

// Scratch (device globals: allocation-free rule)
__device__ float g_k[Bv * Cv * Tv];               // pooled k: [B, C, T]
__device__ float g_attT[(size_t)Bv * Cv * Cv];    // fp32 exp scratch [b][k][m]
__device__ __nv_bfloat16 g_aHi[(size_t)Bv * Cv * Cv];  // att hi bf16 [b][k][m]
__device__ __nv_bfloat16 g_aLo[(size_t)Bv * Cv * Cv];  // att lo bf16 [b][k][m]

// ---------------------------------------------------------------------------
// helpers
// ---------------------------------------------------------------------------
__device__ __forceinline__ uint32_t smem_u32(const void* p) {
    uint32_t a;
    asm("{ .reg .u64 t; cvta.to.shared.u64 t, %1; cvt.u32.u64 %0, t; }" : "=r"(a) : "l"(p));
    return a;
}
// pack two floats as bf16x2 (low half = first arg)
__device__ __forceinline__ uint32_t bpack(float f0, float f1) {
    unsigned short u0 = __bfloat16_as_ushort(__float2bfloat16(f0));
    unsigned short u1 = __bfloat16_as_ushort(__float2bfloat16(f1));
    return (uint32_t)u0 | ((uint32_t)u1 << 16);
}
__device__ __forceinline__ float bres(float f) {   // residual after bf16 truncation
    return f - __bfloat162float(__float2bfloat16(f));
}
__device__ __forceinline__ void ldsm_x4_t(uint32_t& r0, uint32_t& r1, uint32_t& r2,
                                          uint32_t& r3, uint32_t addr) {
    asm volatile("ldmatrix.sync.aligned.m8n8.x4.trans.shared.b16 {%0,%1,%2,%3}, [%4];"
                 : "=r"(r0), "=r"(r1), "=r"(r2), "=r"(r3) : "r"(addr));
}
__device__ __forceinline__ void ldsm_x2_t(uint32_t& r0, uint32_t& r1, uint32_t addr) {
    asm volatile("ldmatrix.sync.aligned.m8n8.x2.trans.shared.b16 {%0,%1}, [%2];"
                 : "=r"(r0), "=r"(r1) : "r"(addr));
}
__device__ __forceinline__ void mma_bf16(float* c, uint32_t a0, uint32_t a1, uint32_t a2,
                                         uint32_t a3, uint32_t b0, uint32_t b1) {
    asm volatile(
        "mma.sync.aligned.m16n8k16.row.col.f32.bf16.bf16.f32 "
        "{%0,%1,%2,%3}, {%4,%5,%6,%7}, {%8,%9}, {%0,%1,%2,%3};"
        : "+f"(c[0]), "+f"(c[1]), "+f"(c[2]), "+f"(c[3])
        : "r"(a0), "r"(a1), "r"(a2), "r"(a3), "r"(b0), "r"(b1));
}

// ---------------------------------------------------------------------------
// Stage 1 (v3): pooling  (measured 42.8us @ 72% DRAM -- at roofline, frozen)
// ---------------------------------------------------------------------------
__global__ __launch_bounds__(384) void pool_kernel(const float* __restrict__ x,
                                                   const float* __restrict__ alpha) {
    __shared__ float a_sm[Nv];
    __shared__ float4 red4[384];
    const int tid = threadIdx.x;
    const int r   = tid / 96;
    const int f0  = tid % 96;
    const int bc  = blockIdx.x * 4 + r;

    for (int i = tid; i < Nv; i += 384) a_sm[i] = alpha[i];
    __syncthreads();

    const float4* xp4 = reinterpret_cast<const float4*>(x) + (size_t)bc * NT4;
    const int i0 = f0 / 3;

    float4 acc = make_float4(0.f, 0.f, 0.f, 0.f);
    {
        float4 vv[5]; float aa[5];
#pragma unroll
        for (int u = 0; u < 5; u++) vv[u] = xp4[f0 + u * 96];
#pragma unroll
        for (int u = 0; u < 5; u++) aa[u] = a_sm[i0 + u * 32];
#pragma unroll
        for (int u = 0; u < 5; u++) {
            acc.x += aa[u] * vv[u].x;  acc.y += aa[u] * vv[u].y;
            acc.z += aa[u] * vv[u].z;  acc.w += aa[u] * vv[u].w;
        }
    }
    {
        float4 vv[4]; float aa[4];
#pragma unroll
        for (int u = 0; u < 4; u++) vv[u] = xp4[f0 + (5 + u) * 96];
#pragma unroll
        for (int u = 0; u < 4; u++) aa[u] = a_sm[i0 + (5 + u) * 32];
#pragma unroll
        for (int u = 0; u < 4; u++) {
            acc.x += aa[u] * vv[u].x;  acc.y += aa[u] * vv[u].y;
            acc.z += aa[u] * vv[u].z;  acc.w += aa[u] * vv[u].w;
        }
    }
    if (f0 + 9 * 96 < NT4) {
        const float a = a_sm[i0 + 9 * 32];
        const float4 v = xp4[f0 + 9 * 96];
        acc.x += a * v.x;  acc.y += a * v.y;
        acc.z += a * v.z;  acc.w += a * v.w;
    }

    red4[tid] = acc;
    __syncthreads();

    if (tid < 48) {
        const int r2 = tid / Tv;
        const int t  = tid % Tv;
        const int g  = t / 4;
        const int e  = t % 4;
        float s = 0.f;
#pragma unroll
        for (int m = 0; m < 32; m++) {
            const float4 v = red4[r2 * 96 + g + 3 * m];
            s += e == 0 ? v.x : (e == 1 ? v.y : (e == 2 ? v.z : v.w));
        }
        g_k[(blockIdx.x * 4 + r2) * Tv + t] = s;
    }
}

// ---------------------------------------------------------------------------
// Stage 2: att = softmax_d(kW k^T), emitted PRE-SPLIT as bf16 hi/lo,
// transposed [b][d][c] (= [k][m] for the GEMM).
// ---------------------------------------------------------------------------
__global__ void att_kernel(const float* __restrict__ W) {
    __shared__ float k_sm[Cv * Tv];
    __shared__ float W_sm[Tv * Tv];
    const int b = blockIdx.x;
    const int c = threadIdx.x;

    for (int i = c; i < Cv * Tv; i += Cv) k_sm[i] = g_k[b * Cv * Tv + i];
    if (c < Tv * Tv) W_sm[c] = W[c];
    __syncthreads();

    float kw[Tv];
#pragma unroll
    for (int t = 0; t < Tv; t++) {
        float s = 0.f;
#pragma unroll
        for (int ss = 0; ss < Tv; ss++) s += k_sm[c * Tv + ss] * W_sm[ss * Tv + t];
        kw[t] = s;
    }

    float m = -1e30f;
    for (int d = 0; d < Cv; d++) {
        float s = 0.f;
#pragma unroll
        for (int t = 0; t < Tv; t++) s += kw[t] * k_sm[d * Tv + t];
        m = fmaxf(m, s);
    }

    float* attT = g_attT + (size_t)b * Cv * Cv;
    float Z = 0.f;
    for (int d = 0; d < Cv; d++) {
        float s = 0.f;
#pragma unroll
        for (int t = 0; t < Tv; t++) s += kw[t] * k_sm[d * Tv + t];
        float e = expf(s - m);
        attT[d * Cv + c] = e;
        Z += e;
    }

    const float inv = 1.f / Z;
    __nv_bfloat16* aHi = g_aHi + (size_t)b * Cv * Cv;
    __nv_bfloat16* aLo = g_aLo + (size_t)b * Cv * Cv;
    for (int d = 0; d < Cv; d++) {
        const float v = attT[d * Cv + c] * inv;
        const __nv_bfloat16 h = __float2bfloat16(v);
        aHi[d * Cv + c] = h;
        aLo[d * Cv + c] = __float2bfloat16(v - __bfloat162float(h));
    }
}

// ---------------------------------------------------------------------------
// Stage 3 (mma.sync bf16 hi/lo split; R12 geometry): out[b] = att[b] @ x[b]
// CTA: 128m x 64n x 32k, 256 thr, 8 warps (4m x 2n), warp tile 32x32.
// A pre-split bf16 in gmem -> pure uint2 copy to smem (no conversion, half
// the A bytes). B converted in-loop (only 2x redundancy). 2 CTAs/SM.
// 3-term split: D += Ah*Bh + Ah*Bl + Al*Bh.
// ---------------------------------------------------------------------------
#define BMm 128
#define BNm 64
#define BKm 32
#define KSTEPS (Cv / BKm)   // 8
#define APITCH 272          // 128 bf16 + 8 pad
#define BPITCH 144          // 64 bf16 + 8 pad

__global__ __launch_bounds__(256) void mix_mma_kernel(const float* __restrict__ x,
                                                      float* __restrict__ out) {
    __shared__ __align__(16) unsigned char Ah[BKm * APITCH];
    __shared__ __align__(16) unsigned char Al[BKm * APITCH];
    __shared__ __align__(16) unsigned char Bh[BKm * BPITCH];
    __shared__ __align__(16) unsigned char Bl[BKm * BPITCH];

    const int tid  = threadIdx.x;
    const int wid  = tid >> 5;
    const int lane = tid & 31;
    const int b    = blockIdx.z;
    const int m0g  = blockIdx.y * BMm;
    const int n0g  = blockIdx.x * BNm;
    const int m_w  = (wid & 3) * 32;   // warp m offset (4 m-warps)
    const int n_w  = (wid >> 2) * 32;  // warp n offset (2 n-warps)

    const __nv_bfloat16* AHi = g_aHi + (size_t)b * Cv * Cv;  // [k=256][m=256]
    const __nv_bfloat16* ALo = g_aLo + (size_t)b * Cv * Cv;
    const float* Bx = x + (size_t)b * Cv * NT;               // [k=256][n=3684]
    float*       O  = out + (size_t)b * Cv * NT;

    const uint32_t sAh = smem_u32(Ah), sAl = smem_u32(Al);
    const uint32_t sBh = smem_u32(Bh), sBl = smem_u32(Bl);

    float acc[2][4][4] = {};   // [msub][nsub][frag]

    // staging registers
    uint2 aHiS[4], aLoS[4];    // bf16x4 each
    float4 bS[2];

    // A loader: pass p -> k = p*8+wid, m = lane*4  (uint2 = 4 bf16)
    // B loader: pass p -> k = p*16 + (tid>>4), n = (lane&15)*4
    const int akl = wid;            // + p*8
    const int aml = lane * 4;
    const int bkl = tid >> 4;       // + p*16
    const int bnl = (lane & 15) * 4;

    // ---- prologue: load tile 0 ----
#pragma unroll
    for (int p = 0; p < 4; p++) {
        const size_t o = (size_t)(p * 8 + akl) * Cv + m0g + aml;
        aHiS[p] = *reinterpret_cast<const uint2*>(AHi + o);
        aLoS[p] = *reinterpret_cast<const uint2*>(ALo + o);
    }
#pragma unroll
    for (int p = 0; p < 2; p++) {
        const int gn = n0g + bnl;
        float4 v = make_float4(0.f, 0.f, 0.f, 0.f);
        if (gn < NT)
            v = *reinterpret_cast<const float4*>(Bx + (size_t)(p * 16 + bkl) * NT + gn);
        bS[p] = v;
    }

#pragma unroll 1
    for (int it = 0; it < KSTEPS; it++) {
        if (it) __syncthreads();   // all warps finished MMA on previous tile

        // ---- STS: A is a straight copy; B converted fp32 -> bf16 hi/lo ----
#pragma unroll
        for (int p = 0; p < 4; p++) {
            const int off = (p * 8 + akl) * APITCH + aml * 2;
            *reinterpret_cast<uint2*>(Ah + off) = aHiS[p];
            *reinterpret_cast<uint2*>(Al + off) = aLoS[p];
        }
#pragma unroll
        for (int p = 0; p < 2; p++) {
            const float4 v = bS[p];
            const int off = (p * 16 + bkl) * BPITCH + bnl * 2;
            *reinterpret_cast<uint2*>(Bh + off) =
                make_uint2(bpack(v.x, v.y), bpack(v.z, v.w));
            *reinterpret_cast<uint2*>(Bl + off) =
                make_uint2(bpack(bres(v.x), bres(v.y)), bpack(bres(v.z), bres(v.w)));
        }
        __syncthreads();

        // ---- prefetch next tile (overlaps MMA below) ----
        if (it + 1 < KSTEPS) {
            const int k0 = (it + 1) * BKm;
#pragma unroll
            for (int p = 0; p < 4; p++) {
                const size_t o = (size_t)(k0 + p * 8 + akl) * Cv + m0g + aml;
                aHiS[p] = *reinterpret_cast<const uint2*>(AHi + o);
                aLoS[p] = *reinterpret_cast<const uint2*>(ALo + o);
            }
#pragma unroll
            for (int p = 0; p < 2; p++) {
                const int gn = n0g + bnl;
                float4 v = make_float4(0.f, 0.f, 0.f, 0.f);
                if (gn < NT)
                    v = *reinterpret_cast<const float4*>(
                        Bx + (size_t)(k0 + p * 16 + bkl) * NT + gn);
                bS[p] = v;
            }
        }

        // ---- MMA over this tile: 2 k16 steps ----
#pragma unroll
        for (int ks = 0; ks < 2; ks++) {
            const int kk = ks * 16 + (lane & 7) + ((lane & 16) >> 1);
            uint32_t ah[2][4], al[2][4];
#pragma unroll
            for (int ms = 0; ms < 2; ms++) {
                const int mm = m_w + ms * 16 + (lane & 8);
                const uint32_t o = (uint32_t)(kk * APITCH + mm * 2);
                ldsm_x4_t(ah[ms][0], ah[ms][1], ah[ms][2], ah[ms][3], sAh + o);
                ldsm_x4_t(al[ms][0], al[ms][1], al[ms][2], al[ms][3], sAl + o);
            }
            const int bkk = ks * 16 + (lane & 15);
            uint32_t bh[4][2], bl[4][2];
#pragma unroll
            for (int ns = 0; ns < 4; ns++) {
                const uint32_t o = (uint32_t)(bkk * BPITCH + (n_w + ns * 8) * 2);
                ldsm_x2_t(bh[ns][0], bh[ns][1], sBh + o);
                ldsm_x2_t(bl[ns][0], bl[ns][1], sBl + o);
            }
#pragma unroll
            for (int ms = 0; ms < 2; ms++)
#pragma unroll
                for (int ns = 0; ns < 4; ns++) {
                    mma_bf16(acc[ms][ns], ah[ms][0], ah[ms][1], ah[ms][2], ah[ms][3],
                             bh[ns][0], bh[ns][1]);
                    mma_bf16(acc[ms][ns], ah[ms][0], ah[ms][1], ah[ms][2], ah[ms][3],
                             bl[ns][0], bl[ns][1]);
                    mma_bf16(acc[ms][ns], al[ms][0], al[ms][1], al[ms][2], al[ms][3],
                             bh[ns][0], bh[ns][1]);
                }
        }
    }

    // ---- epilogue ----
#pragma unroll
    for (int ms = 0; ms < 2; ms++)
#pragma unroll
        for (int ns = 0; ns < 4; ns++) {
            const int row = m0g + m_w + ms * 16 + (lane >> 2);
            const int col = n0g + n_w + ns * 8 + (lane & 3) * 2;
            if (col < NT) {
                float2 v0 = make_float2(acc[ms][ns][0], acc[ms][ns][1]);
                float2 v1 = make_float2(acc[ms][ns][2], acc[ms][ns][3]);
                *reinterpret_cast<float2*>(O + (size_t)row * NT + col) = v0;
                *reinterpret_cast<float2*>(O + (size_t)(row + 8) * NT + col) = v1;
            }
        }
}

// ---------------------------------------------------------------------------
extern "C" void kernel_launch(void* const* d_in, const int* in_sizes, int n_in,
                              void* d_out, int out_size) {
    const float* x     = (const float*)d_in[0];  // [64,256,307,12]
    const float* W     = (const float*)d_in[1];  // [12,12]
    const float* alpha = (const float*)d_in[2];  // [307]
    float*       out   = (float*)d_out;          // [64,256,307,12]

    pool_kernel<<<Bv * Cv / 4, 384>>>(x, alpha);
    att_kernel<<<Bv, Cv>>>(W);

    dim3 grid((NT + BNm - 1) / BNm, Cv / BMm, Bv);  // (58, 2, 64)
    mix_mma_kernel<<<grid, 256>>>(x, out);
}

// round 17
// speedup vs baseline: 1.2363x; 1.1061x over previous
#include <cuda_runtime.h>
#include <cuda_bf16.h>
#include <cstdint>

// Problem constants
#define Bv 64
#define Cv 256
#define Nv 307
#define Tv 12
#define NT (Nv * Tv)     // 3684
#define NT4 (NT / 4)     // 921

// Scratch (device globals: allocation-free rule)
__device__ float g_k[Bv * Cv * Tv];             // pooled k: [B, C, T]
__device__ float g_attT[(size_t)Bv * Cv * Cv];  // att TRANSPOSED [b][k][m], tf32-rounded

// ---------------------------------------------------------------------------
// helpers
// ---------------------------------------------------------------------------
__device__ __forceinline__ uint32_t smem_u32(const void* p) {
    uint32_t a;
    asm("{ .reg .u64 t; cvta.to.shared.u64 t, %1; cvt.u32.u64 %0, t; }" : "=r"(a) : "l"(p));
    return a;
}
// round-to-nearest tf32 (keeps f32 bit layout, low mantissa zeroed)
__device__ __forceinline__ float tf32r(float f) {
    uint32_t u;
    asm("cvt.rna.tf32.f32 %0, %1;" : "=r"(u) : "f"(f));
    return __uint_as_float(u);
}
__device__ __forceinline__ void mma_tf32(float* c, uint32_t a0, uint32_t a1, uint32_t a2,
                                         uint32_t a3, uint32_t b0, uint32_t b1) {
    asm volatile(
        "mma.sync.aligned.m16n8k8.row.col.f32.tf32.tf32.f32 "
        "{%0,%1,%2,%3}, {%4,%5,%6,%7}, {%8,%9}, {%0,%1,%2,%3};"
        : "+f"(c[0]), "+f"(c[1]), "+f"(c[2]), "+f"(c[3])
        : "r"(a0), "r"(a1), "r"(a2), "r"(a3), "r"(b0), "r"(b1));
}

// ---------------------------------------------------------------------------
// Stage 1 (v3): pooling  (measured 42.8us @ 72% DRAM -- at roofline, frozen)
// ---------------------------------------------------------------------------
__global__ __launch_bounds__(384) void pool_kernel(const float* __restrict__ x,
                                                   const float* __restrict__ alpha) {
    __shared__ float a_sm[Nv];
    __shared__ float4 red4[384];
    const int tid = threadIdx.x;
    const int r   = tid / 96;
    const int f0  = tid % 96;
    const int bc  = blockIdx.x * 4 + r;

    for (int i = tid; i < Nv; i += 384) a_sm[i] = alpha[i];
    __syncthreads();

    const float4* xp4 = reinterpret_cast<const float4*>(x) + (size_t)bc * NT4;
    const int i0 = f0 / 3;

    float4 acc = make_float4(0.f, 0.f, 0.f, 0.f);
    {
        float4 vv[5]; float aa[5];
#pragma unroll
        for (int u = 0; u < 5; u++) vv[u] = xp4[f0 + u * 96];
#pragma unroll
        for (int u = 0; u < 5; u++) aa[u] = a_sm[i0 + u * 32];
#pragma unroll
        for (int u = 0; u < 5; u++) {
            acc.x += aa[u] * vv[u].x;  acc.y += aa[u] * vv[u].y;
            acc.z += aa[u] * vv[u].z;  acc.w += aa[u] * vv[u].w;
        }
    }
    {
        float4 vv[4]; float aa[4];
#pragma unroll
        for (int u = 0; u < 4; u++) vv[u] = xp4[f0 + (5 + u) * 96];
#pragma unroll
        for (int u = 0; u < 4; u++) aa[u] = a_sm[i0 + (5 + u) * 32];
#pragma unroll
        for (int u = 0; u < 4; u++) {
            acc.x += aa[u] * vv[u].x;  acc.y += aa[u] * vv[u].y;
            acc.z += aa[u] * vv[u].z;  acc.w += aa[u] * vv[u].w;
        }
    }
    if (f0 + 9 * 96 < NT4) {
        const float a = a_sm[i0 + 9 * 32];
        const float4 v = xp4[f0 + 9 * 96];
        acc.x += a * v.x;  acc.y += a * v.y;
        acc.z += a * v.z;  acc.w += a * v.w;
    }

    red4[tid] = acc;
    __syncthreads();

    if (tid < 48) {
        const int r2 = tid / Tv;
        const int t  = tid % Tv;
        const int g  = t / 4;
        const int e  = t % 4;
        float s = 0.f;
#pragma unroll
        for (int m = 0; m < 32; m++) {
            const float4 v = red4[r2 * 96 + g + 3 * m];
            s += e == 0 ? v.x : (e == 1 ? v.y : (e == 2 ? v.z : v.w));
        }
        g_k[(blockIdx.x * 4 + r2) * Tv + t] = s;
    }
}

// ---------------------------------------------------------------------------
// Stage 2: att = softmax_d(kW k^T), stored TRANSPOSED [b][d][c] and
// PRE-ROUNDED to tf32 (round-to-nearest) for the tensor-core GEMM.
// ---------------------------------------------------------------------------
__global__ void att_kernel(const float* __restrict__ W) {
    __shared__ float k_sm[Cv * Tv];
    __shared__ float W_sm[Tv * Tv];
    const int b = blockIdx.x;
    const int c = threadIdx.x;

    for (int i = c; i < Cv * Tv; i += Cv) k_sm[i] = g_k[b * Cv * Tv + i];
    if (c < Tv * Tv) W_sm[c] = W[c];
    __syncthreads();

    float kw[Tv];
#pragma unroll
    for (int t = 0; t < Tv; t++) {
        float s = 0.f;
#pragma unroll
        for (int ss = 0; ss < Tv; ss++) s += k_sm[c * Tv + ss] * W_sm[ss * Tv + t];
        kw[t] = s;
    }

    float m = -1e30f;
    for (int d = 0; d < Cv; d++) {
        float s = 0.f;
#pragma unroll
        for (int t = 0; t < Tv; t++) s += kw[t] * k_sm[d * Tv + t];
        m = fmaxf(m, s);
    }

    float* attT = g_attT + (size_t)b * Cv * Cv;
    float Z = 0.f;
    for (int d = 0; d < Cv; d++) {
        float s = 0.f;
#pragma unroll
        for (int t = 0; t < Tv; t++) s += kw[t] * k_sm[d * Tv + t];
        float e = expf(s - m);
        attT[d * Cv + c] = e;
        Z += e;
    }

    const float inv = 1.f / Z;
    for (int d = 0; d < Cv; d++)
        attT[d * Cv + c] = tf32r(attT[d * Cv + c] * inv);   // tf32-rounded
}

// ---------------------------------------------------------------------------
// Stage 3 (tf32 mma.sync m16n8k8, single pass): out[b] = att[b] @ x[b]
// CTA: 128m x 64n x 32k, 256 thr, 8 warps (4m x 2n), warp tile 32x32.
// Fragments via plain LDS.32 (pitch mod 32 = 8). A pre-rounded tf32 in gmem;
// B rounded at STS. 2 MMAs per 16k per subtile (vs bf16 3-term's 3).
// ---------------------------------------------------------------------------
#define BMm 128
#define BNm 64
#define BKm 32
#define KSTEPS (Cv / BKm)   // 8
#define AP 136              // A row pitch in floats (128 + 8); 136 % 32 == 8
#define BP 72               // B row pitch in floats (64 + 8);  72 % 32 == 8

__global__ __launch_bounds__(256, 2) void mix_mma_kernel(const float* __restrict__ x,
                                                         float* __restrict__ out) {
    __shared__ __align__(16) float As[BKm * AP];   // [k][m] fp32(tf32) 17.4 KB
    __shared__ __align__(16) float Bs[BKm * BP];   // [k][n] fp32(tf32)  9.2 KB

    const int tid  = threadIdx.x;
    const int wid  = tid >> 5;
    const int lane = tid & 31;
    const int b    = blockIdx.z;
    const int m0g  = blockIdx.y * BMm;
    const int n0g  = blockIdx.x * BNm;
    const int m_w  = (wid & 3) * 32;   // warp m offset (4 m-warps)
    const int n_w  = (wid >> 2) * 32;  // warp n offset (2 n-warps)

    const float* AT = g_attT + (size_t)b * Cv * Cv;  // [k=256][m=256], tf32
    const float* Bx = x + (size_t)b * Cv * NT;       // [k=256][n=3684]
    float*       O  = out + (size_t)b * Cv * NT;

    float acc[2][4][4] = {};   // [msub(16)][nsub(8)][frag]

    // staging registers
    float4 aS[4], bS[2];

    // A loader: pass p -> k = p*8 + wid, m = lane*4
    // B loader: pass p -> k = p*16 + (tid>>4), n = (tid&15)*4
    const int akl = wid;
    const int aml = lane * 4;
    const int bkl = tid >> 4;
    const int bnl = (tid & 15) * 4;

    // fragment LDS indices (per warp, lane-dependent)
    const int fk = lane & 3;          // k within 4
    const int fr = lane >> 2;         // 0..7 (m-row or n-col)

    // ---- prologue: load tile 0 ----
#pragma unroll
    for (int p = 0; p < 4; p++)
        aS[p] = *reinterpret_cast<const float4*>(AT + (size_t)(p * 8 + akl) * Cv + m0g + aml);
#pragma unroll
    for (int p = 0; p < 2; p++) {
        const int gn = n0g + bnl;
        float4 v = make_float4(0.f, 0.f, 0.f, 0.f);
        if (gn < NT)   // NT % 4 == 0: float4-safe predication
            v = *reinterpret_cast<const float4*>(Bx + (size_t)(p * 16 + bkl) * NT + gn);
        bS[p] = v;
    }

#pragma unroll 1
    for (int it = 0; it < KSTEPS; it++) {
        if (it) __syncthreads();   // all warps finished MMA on previous tile

        // ---- STS: A straight copy (already tf32); B rounded to tf32 ----
#pragma unroll
        for (int p = 0; p < 4; p++)
            *reinterpret_cast<float4*>(&As[(p * 8 + akl) * AP + aml]) = aS[p];
#pragma unroll
        for (int p = 0; p < 2; p++) {
            const float4 v = bS[p];
            *reinterpret_cast<float4*>(&Bs[(p * 16 + bkl) * BP + bnl]) =
                make_float4(tf32r(v.x), tf32r(v.y), tf32r(v.z), tf32r(v.w));
        }
        __syncthreads();

        // ---- prefetch next tile (overlaps MMA below) ----
        if (it + 1 < KSTEPS) {
            const int k0 = (it + 1) * BKm;
#pragma unroll
            for (int p = 0; p < 4; p++)
                aS[p] = *reinterpret_cast<const float4*>(
                    AT + (size_t)(k0 + p * 8 + akl) * Cv + m0g + aml);
#pragma unroll
            for (int p = 0; p < 2; p++) {
                const int gn = n0g + bnl;
                float4 v = make_float4(0.f, 0.f, 0.f, 0.f);
                if (gn < NT)
                    v = *reinterpret_cast<const float4*>(
                        Bx + (size_t)(k0 + p * 16 + bkl) * NT + gn);
                bS[p] = v;
            }
        }

        // ---- MMA over this tile: 4 k8 steps ----
#pragma unroll
        for (int ks = 0; ks < 4; ks++) {
            const int kb = ks * 8;
            // B fragments: b0 = (k = kb+fk, n = n_w+ns*8+fr), b1 = k+4
            uint32_t bf[4][2];
#pragma unroll
            for (int ns = 0; ns < 4; ns++) {
                const int nn = n_w + ns * 8 + fr;
                bf[ns][0] = __float_as_uint(Bs[(kb + fk) * BP + nn]);
                bf[ns][1] = __float_as_uint(Bs[(kb + fk + 4) * BP + nn]);
            }
            // A fragments per ms: a0=(m=mq+fr, k=kb+fk), a1=m+8, a2=k+4, a3=both
#pragma unroll
            for (int ms = 0; ms < 2; ms++) {
                const int mq = m_w + ms * 16 + fr;
                uint32_t a0 = __float_as_uint(As[(kb + fk) * AP + mq]);
                uint32_t a1 = __float_as_uint(As[(kb + fk) * AP + mq + 8]);
                uint32_t a2 = __float_as_uint(As[(kb + fk + 4) * AP + mq]);
                uint32_t a3 = __float_as_uint(As[(kb + fk + 4) * AP + mq + 8]);
#pragma unroll
                for (int ns = 0; ns < 4; ns++)
                    mma_tf32(acc[ms][ns], a0, a1, a2, a3, bf[ns][0], bf[ns][1]);
            }
        }
    }

    // ---- epilogue ----
    // c0,c1: (row = lane/4, col = (lane%4)*2 + {0,1}); c2,c3: row+8
#pragma unroll
    for (int ms = 0; ms < 2; ms++)
#pragma unroll
        for (int ns = 0; ns < 4; ns++) {
            const int row = m0g + m_w + ms * 16 + (lane >> 2);
            const int col = n0g + n_w + ns * 8 + (lane & 3) * 2;
            if (col < NT) {
                float2 v0 = make_float2(acc[ms][ns][0], acc[ms][ns][1]);
                float2 v1 = make_float2(acc[ms][ns][2], acc[ms][ns][3]);
                *reinterpret_cast<float2*>(O + (size_t)row * NT + col) = v0;
                *reinterpret_cast<float2*>(O + (size_t)(row + 8) * NT + col) = v1;
            }
        }
}

// ---------------------------------------------------------------------------
extern "C" void kernel_launch(void* const* d_in, const int* in_sizes, int n_in,
                              void* d_out, int out_size) {
    const float* x     = (const float*)d_in[0];  // [64,256,307,12]
    const float* W     = (const float*)d_in[1];  // [12,12]
    const float* alpha = (const float*)d_in[2];  // [307]
    float*       out   = (float*)d_out;          // [64,256,307,12]

    pool_kernel<<<Bv * Cv / 4, 384>>>(x, alpha);
    att_kernel<<<Bv, Cv>>>(W);

    dim3 grid((NT + BNm - 1) / BNm, Cv / BMm, Bv);  // (58, 2, 64)
    mix_mma_kernel<<<grid, 256>>>(x, out);
}